// round 9
// baseline (speedup 1.0000x reference)
#include <cuda_runtime.h>
#include <cstdint>

// Problem constants
#define Bc   8
#define Tc   256
#define Uc   64
#define Dc   640
#define Vc   1024
#define K2c  1280
#define MOUT (Bc*Tc*Uc)     // 131072 output rows
#define NIT  (Dc/32)        // 20 k-iterations

// Pre-transformed operands (tf32 bit patterns stored as float)
__device__ __align__(16) float g_encT [Bc*Tc*Dc];   // relu+tf32(enc)
__device__ __align__(16) float g_predT[Bc*Uc*Dc];   // relu+tf32(pred)
__device__ __align__(16) float g_Wtf  [Vc*K2c];     // tf32(W)

__device__ __forceinline__ uint32_t f2tf(float x) {
    uint32_t r;
    asm("cvt.rna.tf32.f32 %0, %1;" : "=r"(r) : "f"(x));
    return r;
}
__device__ __forceinline__ void cpa(uint32_t dst, const float* src) {
    asm volatile("cp.async.ca.shared.global [%0], [%1], 16;\n"
                 :: "r"(dst), "l"(src));
}
#define CP_COMMIT() asm volatile("cp.async.commit_group;\n" ::: "memory")
#define CP_WAIT2()  asm volatile("cp.async.wait_group 2;\n" ::: "memory")
#define CP_WAIT0()  asm volatile("cp.async.wait_group 0;\n" ::: "memory")

// ---------------------------------------------------------------------------
// Prologue: relu+tf32 transform of enc/pred, tf32 of W; writes length tail.
// ---------------------------------------------------------------------------
#define NE4 (Bc*Tc*Dc/4)
#define NP4 (Bc*Uc*Dc/4)
#define NW4 (Vc*K2c/4)
__global__ __launch_bounds__(256) void transform_kernel(
    const float4* __restrict__ enc,
    const float4* __restrict__ pred,
    const float4* __restrict__ W,
    float* __restrict__ out,
    const int* __restrict__ slen,
    const int* __restrict__ tlen,
    int writeTail)
{
    int idx = blockIdx.x * 256 + threadIdx.x;
    float4 v; float4* dst;
    if (idx < NE4) {
        v = enc[idx];
        v.x = fmaxf(v.x, 0.f); v.y = fmaxf(v.y, 0.f);
        v.z = fmaxf(v.z, 0.f); v.w = fmaxf(v.w, 0.f);
        dst = ((float4*)g_encT) + idx;
    } else if (idx < NE4 + NP4) {
        v = pred[idx - NE4];
        v.x = fmaxf(v.x, 0.f); v.y = fmaxf(v.y, 0.f);
        v.z = fmaxf(v.z, 0.f); v.w = fmaxf(v.w, 0.f);
        dst = ((float4*)g_predT) + (idx - NE4);
    } else if (idx < NE4 + NP4 + NW4) {
        v = W[idx - NE4 - NP4];
        dst = ((float4*)g_Wtf) + (idx - NE4 - NP4);
    } else {
        return;
    }
    uint4 o;
    o.x = f2tf(v.x); o.y = f2tf(v.y); o.z = f2tf(v.z); o.w = f2tf(v.w);
    *(uint4*)dst = o;

    if (writeTail && blockIdx.x == 0 && threadIdx.x < 16) {
        size_t tb = (size_t)MOUT * Vc;
        int t = threadIdx.x;
        if (t < 8) out[tb + t] = (float)slen[t];
        else       out[tb + t] = (float)tlen[t - 8];
    }
}

// 172 KB dynamic shared memory, 1 block/SM
struct __align__(16) Smem {
    float    P[64][128];        // 32 KB  P tile (+bias), persistent
    float    E[2][32][128];     // 32 KB  E slab double buffer
    uint32_t As[4][64][36];     // 36 KB  A staging ring (P: 64 rows; slabs: 32)
    uint32_t Bs[4][128][36];    // 72 KB  W staging ring
};

// ---------------------------------------------------------------------------
// Main kernel. grid = (V/128=8, 2*B=16), 512 threads (16 warps), 1 blk/SM.
//   Block (bx,by): b = by>>1, t0 = (by&1)*128, v-cols [bx*128, +128)
// Phase P: P[64u x 128v] -> smem (pipelined)
// Slab loop s=0..3 (all 16 warps): gemm E slab (32t x 128v) -> E[s&1],
//   prefetch slab s+1, then store slab s. Stores drain under next slab's gemm.
// ---------------------------------------------------------------------------
__global__ __launch_bounds__(512, 1) void fused_joiner(
    const float* __restrict__ bias,
    float4* __restrict__ out)
{
    extern __shared__ char smem_raw[];
    Smem& sm = *reinterpret_cast<Smem*>(smem_raw);

    const int tid  = threadIdx.x;
    const int warp = tid >> 5;
    const int lane = tid & 31;
    const int g    = lane >> 2;
    const int q    = lane & 3;
    const int bn0  = blockIdx.x * 128;
    const int b    = blockIdx.y >> 1;
    const int bt0  = b * Tc + (blockIdx.y & 1) * 128;

    const int lr = tid >> 3;        // 0..63
    const int lc = (tid & 7) * 4;   // 0,4..28

    const uint32_t asB = (uint32_t)__cvta_generic_to_shared(sm.As);
    const uint32_t bsB = (uint32_t)__cvta_generic_to_shared(sm.Bs);
    auto aoff = [](int st, int row, int col) -> uint32_t {
        return (uint32_t)((((st * 64 + row) * 36) + col) * 4);
    };
    auto boff = [](int st, int row, int col) -> uint32_t {
        return (uint32_t)((((st * 128 + row) * 36) + col) * 4);
    };

    // W staging issue (same for P phase kOff=Dc and E slabs kOff=0)
    auto issueW = [&](int st, int kOff, int k0) {
        cpa(bsB + boff(st, lr, lc),
            &g_Wtf[(size_t)(bn0 + lr) * K2c + kOff + k0 + lc]);
        cpa(bsB + boff(st, lr + 64, lc),
            &g_Wtf[(size_t)(bn0 + lr + 64) * K2c + kOff + k0 + lc]);
    };

    // ===================== Phase P: 64 x 128 =====================
    {
        auto issueP = [&](int st, int k0) {
            cpa(asB + aoff(st, lr, lc),
                &g_predT[(size_t)(b * Uc + lr) * Dc + k0 + lc]);
            issueW(st, Dc, k0);
        };

        const int mgP = warp & 3;
        const int ngP = warp >> 2;
        float cP[4][4];
#pragma unroll
        for (int nt = 0; nt < 4; nt++)
#pragma unroll
            for (int r = 0; r < 4; r++) cP[nt][r] = 0.f;

        issueP(0, 0);  CP_COMMIT();
        issueP(1, 32); CP_COMMIT();

#pragma unroll 1
        for (int it = 0; it < NIT; it++) {
            const int st = it & 3;
            const int nx = it + 2;
            if (nx < NIT) issueP(nx & 3, nx * 32);
            CP_COMMIT();
            CP_WAIT2();
            __syncthreads();
#pragma unroll
            for (int kk = 0; kk < 4; kk++) {
                uint32_t af[4];
                af[0] = sm.As[st][mgP*16 + g    ][kk*8 + q    ];
                af[1] = sm.As[st][mgP*16 + g + 8][kk*8 + q    ];
                af[2] = sm.As[st][mgP*16 + g    ][kk*8 + q + 4];
                af[3] = sm.As[st][mgP*16 + g + 8][kk*8 + q + 4];
#pragma unroll
                for (int nt = 0; nt < 4; nt++) {
                    int n = ngP*32 + nt*8 + g;
                    uint32_t b0 = sm.Bs[st][n][kk*8 + q];
                    uint32_t b1 = sm.Bs[st][n][kk*8 + q + 4];
                    asm volatile(
                        "mma.sync.aligned.m16n8k8.row.col.f32.tf32.tf32.f32 "
                        "{%0,%1,%2,%3}, {%4,%5,%6,%7}, {%8,%9}, {%0,%1,%2,%3};\n"
                        : "+f"(cP[nt][0]), "+f"(cP[nt][1]), "+f"(cP[nt][2]), "+f"(cP[nt][3])
                        : "r"(af[0]), "r"(af[1]), "r"(af[2]), "r"(af[3]),
                          "r"(b0), "r"(b1));
                }
            }
        }
        CP_WAIT0();
        __syncthreads();

        // dump P (+bias) to persistent smem (ordered by slab-0 loop barriers)
        int r0 = mgP * 16 + g;
#pragma unroll
        for (int nt = 0; nt < 4; nt++) {
            int col = ngP*32 + nt*8 + q*2;
            float b0 = bias[bn0 + col];
            float b1 = bias[bn0 + col + 1];
            sm.P[r0    ][col    ] = cP[nt][0] + b0;
            sm.P[r0    ][col + 1] = cP[nt][1] + b1;
            sm.P[r0 + 8][col    ] = cP[nt][2] + b0;
            sm.P[r0 + 8][col + 1] = cP[nt][3] + b1;
        }
    }

    // ===================== Slab loop: gemm + store interleave ==============
    // Slab gemm: M=32, N=128; warp tile 16 rows x 16 cols (mg=warp&1, ng=warp>>1)
    const int mg = warp & 1;
    const int ng = warp >> 1;
    const int vq = lane;

    auto issueS = [&](int st, int s, int k0) {
        if (tid < 256) {
            int plr = tid >> 3;          // 0..31
            int plc = (tid & 7) * 4;
            cpa(asB + aoff(st, plr, plc),
                &g_encT[(size_t)(bt0 + s * 32 + plr) * Dc + k0 + plc]);
        }
        issueW(st, 0, k0);
    };

    // prologue for slab 0
    issueS(0, 0, 0);  CP_COMMIT();
    issueS(1, 0, 32); CP_COMMIT();

#pragma unroll 1
    for (int s = 0; s < 4; s++) {
        float c[2][4];
#pragma unroll
        for (int nt = 0; nt < 2; nt++)
#pragma unroll
            for (int r = 0; r < 4; r++) c[nt][r] = 0.f;

#pragma unroll 1
        for (int it = 0; it < NIT; it++) {
            const int st = it & 3;
            const int nx = it + 2;
            if (nx < NIT) issueS(nx & 3, s, nx * 32);
            CP_COMMIT();
            CP_WAIT2();
            __syncthreads();
#pragma unroll
            for (int kk = 0; kk < 4; kk++) {
                uint32_t af[4];
                af[0] = sm.As[st][mg*16 + g    ][kk*8 + q    ];
                af[1] = sm.As[st][mg*16 + g + 8][kk*8 + q    ];
                af[2] = sm.As[st][mg*16 + g    ][kk*8 + q + 4];
                af[3] = sm.As[st][mg*16 + g + 8][kk*8 + q + 4];
#pragma unroll
                for (int nt = 0; nt < 2; nt++) {
                    int n = ng*16 + nt*8 + g;
                    uint32_t b0 = sm.Bs[st][n][kk*8 + q];
                    uint32_t b1 = sm.Bs[st][n][kk*8 + q + 4];
                    asm volatile(
                        "mma.sync.aligned.m16n8k8.row.col.f32.tf32.tf32.f32 "
                        "{%0,%1,%2,%3}, {%4,%5,%6,%7}, {%8,%9}, {%0,%1,%2,%3};\n"
                        : "+f"(c[nt][0]), "+f"(c[nt][1]), "+f"(c[nt][2]), "+f"(c[nt][3])
                        : "r"(af[0]), "r"(af[1]), "r"(af[2]), "r"(af[3]),
                          "r"(b0), "r"(b1));
                }
            }
        }
        CP_WAIT0();
        __syncthreads();

        // dump slab accumulators to E[s&1]
        {
            float (*Eb)[128] = sm.E[s & 1];
            int r0 = mg * 16 + g;
#pragma unroll
            for (int nt = 0; nt < 2; nt++) {
                int col = ng*16 + nt*8 + q*2;
                Eb[r0    ][col    ] = c[nt][0];
                Eb[r0    ][col + 1] = c[nt][1];
                Eb[r0 + 8][col    ] = c[nt][2];
                Eb[r0 + 8][col + 1] = c[nt][3];
            }
        }
        __syncthreads();

        // prefetch next slab's first two k-tiles BEFORE storing (overlaps)
        if (s < 3) {
            issueS(0, s + 1, 0);  CP_COMMIT();
            issueS(1, s + 1, 32); CP_COMMIT();
        }

        // store slab s: warp stores rows {2w, 2w+1}; per u: 1 LDS + 2 STG.cs
        {
            const float (*Eb)[128] = sm.E[s & 1];
            float4 e0 = ((const float4*)Eb[warp * 2    ])[vq];
            float4 e1 = ((const float4*)Eb[warp * 2 + 1])[vq];
            size_t ob0 = (size_t)(bt0 + s * 32 + warp * 2) * (Uc * 256)
                         + blockIdx.x * 32 + vq;
            size_t ob1 = ob0 + (size_t)(Uc * 256);
#pragma unroll 4
            for (int u = 0; u < Uc; u++) {
                float4 p = ((const float4*)sm.P[u])[vq];
                float4 r0, r1;
                r0.x = e0.x + p.x; r0.y = e0.y + p.y; r0.z = e0.z + p.z; r0.w = e0.w + p.w;
                r1.x = e1.x + p.x; r1.y = e1.y + p.y; r1.z = e1.z + p.z; r1.w = e1.w + p.w;
                __stcs(&out[ob0 + (size_t)u * 256], r0);
                __stcs(&out[ob1 + (size_t)u * 256], r1);
            }
        }
        // no barrier: next slab's k-loop barriers provide ordering; stores
        // drain in the background while slab s+1 computes.
    }
}

extern "C" void kernel_launch(void* const* d_in, const int* in_sizes, int n_in,
                              void* d_out, int out_size)
{
    const float* enc  = (const float*)d_in[0];  // [B,T,D]
    const int*   slen = (const int*)  d_in[1];  // [B]
    const float* pred = (const float*)d_in[2];  // [B,U,D]
    const int*   tlen = (const int*)  d_in[3];  // [B]
    const float* W    = (const float*)d_in[4];  // [V, 2D]
    const float* bias = (const float*)d_in[5];  // [V]
    float* out = (float*)d_out;

    int writeTail = (out_size >= (int)((size_t)MOUT * Vc + 16)) ? 1 : 0;

    int nTot = NE4 + NP4 + NW4;
    transform_kernel<<<(nTot + 255) / 256, 256>>>(
        (const float4*)enc, (const float4*)pred, (const float4*)W,
        out, slen, tlen, writeTail);

    int smemBytes = (int)sizeof(Smem);
    cudaFuncSetAttribute(fused_joiner,
                         cudaFuncAttributeMaxDynamicSharedMemorySize, smemBytes);
    fused_joiner<<<dim3(Vc / 128, 2 * Bc), 512, smemBytes>>>(
        bias, (float4*)out);
}

// round 10
// speedup vs baseline: 1.1615x; 1.1615x over previous
#include <cuda_runtime.h>
#include <cstdint>

// Problem constants
#define Bc   8
#define Tc   256
#define Uc   64
#define Dc   640
#define Vc   1024
#define K2c  1280
#define MOUT (Bc*Tc*Uc)     // 131072 output rows
#define NIT  (Dc/32)        // 20 k-iterations

// Pre-transformed operands (tf32 bit patterns stored as float)
__device__ __align__(16) float g_encT [Bc*Tc*Dc];   // relu+tf32(enc)
__device__ __align__(16) float g_predT[Bc*Uc*Dc];   // relu+tf32(pred)
__device__ __align__(16) float g_Wtf  [Vc*K2c];     // tf32(W)

__device__ __forceinline__ uint32_t f2tf(float x) {
    uint32_t r;
    asm("cvt.rna.tf32.f32 %0, %1;" : "=r"(r) : "f"(x));
    return r;
}
__device__ __forceinline__ void cpa(uint32_t dst, const float* src) {
    asm volatile("cp.async.ca.shared.global [%0], [%1], 16;\n"
                 :: "r"(dst), "l"(src));
}
#define CP_COMMIT() asm volatile("cp.async.commit_group;\n" ::: "memory")
#define CP_WAIT2()  asm volatile("cp.async.wait_group 2;\n" ::: "memory")
#define CP_WAIT0()  asm volatile("cp.async.wait_group 0;\n" ::: "memory")

// ---------------------------------------------------------------------------
// Prologue: relu+tf32 transform of enc/pred, tf32 of W; writes length tail.
// ---------------------------------------------------------------------------
#define NE4 (Bc*Tc*Dc/4)
#define NP4 (Bc*Uc*Dc/4)
#define NW4 (Vc*K2c/4)
__global__ __launch_bounds__(256) void transform_kernel(
    const float4* __restrict__ enc,
    const float4* __restrict__ pred,
    const float4* __restrict__ W,
    float* __restrict__ out,
    const int* __restrict__ slen,
    const int* __restrict__ tlen,
    int writeTail)
{
    int idx = blockIdx.x * 256 + threadIdx.x;
    float4 v; float4* dst;
    if (idx < NE4) {
        v = enc[idx];
        v.x = fmaxf(v.x, 0.f); v.y = fmaxf(v.y, 0.f);
        v.z = fmaxf(v.z, 0.f); v.w = fmaxf(v.w, 0.f);
        dst = ((float4*)g_encT) + idx;
    } else if (idx < NE4 + NP4) {
        v = pred[idx - NE4];
        v.x = fmaxf(v.x, 0.f); v.y = fmaxf(v.y, 0.f);
        v.z = fmaxf(v.z, 0.f); v.w = fmaxf(v.w, 0.f);
        dst = ((float4*)g_predT) + (idx - NE4);
    } else if (idx < NE4 + NP4 + NW4) {
        v = W[idx - NE4 - NP4];
        dst = ((float4*)g_Wtf) + (idx - NE4 - NP4);
    } else {
        return;
    }
    uint4 o;
    o.x = f2tf(v.x); o.y = f2tf(v.y); o.z = f2tf(v.z); o.w = f2tf(v.w);
    *(uint4*)dst = o;

    if (writeTail && blockIdx.x == 0 && threadIdx.x < 16) {
        size_t tb = (size_t)MOUT * Vc;
        int t = threadIdx.x;
        if (t < 8) out[tb + t] = (float)slen[t];
        else       out[tb + t] = (float)tlen[t - 8];
    }
}

// 192 KB dynamic shared memory, 1 block/SM
struct __align__(16) Smem {
    float    P[64][128];        // 32 KB  P tile (+bias), persistent
    float    E[32][128];        // 16 KB  store-phase slab
    uint32_t As[4][128][36];    // 72 KB  A staging, 4-stage ring
    uint32_t Bs[4][128][36];    // 72 KB  W staging, 4-stage ring
};

// ---------------------------------------------------------------------------
// Main kernel (R8 structure). grid = (V/128=8, 2*B=16), 512 threads.
// Phase P: P[64u x 128v] -> smem (cp.async pipelined gemm)
// Phase E: cE[128t x 128v] in regs (cp.async pipelined gemm)
// Phase C: 4 slabs of 32 t: out = E + P, WRITE-THROUGH stores (the one change)
// ---------------------------------------------------------------------------
__global__ __launch_bounds__(512, 1) void fused_joiner(
    const float* __restrict__ bias,
    float4* __restrict__ out)
{
    extern __shared__ char smem_raw[];
    Smem& sm = *reinterpret_cast<Smem*>(smem_raw);

    const int tid  = threadIdx.x;
    const int warp = tid >> 5;
    const int lane = tid & 31;
    const int g    = lane >> 2;
    const int q    = lane & 3;
    const int bn0  = blockIdx.x * 128;
    const int b    = blockIdx.y >> 1;
    const int bt0  = b * Tc + (blockIdx.y & 1) * 128;

    const int lr = tid >> 3;        // 0..63
    const int lc = (tid & 7) * 4;   // 0,4..28

    const uint32_t asB = (uint32_t)__cvta_generic_to_shared(sm.As);
    const uint32_t bsB = (uint32_t)__cvta_generic_to_shared(sm.Bs);
    auto soff = [](int st, int row, int col) -> uint32_t {
        return (uint32_t)((((st * 128 + row) * 36) + col) * 4);
    };

    // ===================== Phase P: 64 x 128 =====================
    {
        auto issueP = [&](int st, int k0) {
            cpa(asB + soff(st, lr, lc),
                &g_predT[(size_t)(b * Uc + lr) * Dc + k0 + lc]);
            cpa(bsB + soff(st, lr, lc),
                &g_Wtf[(size_t)(bn0 + lr) * K2c + Dc + k0 + lc]);
            cpa(bsB + soff(st, lr + 64, lc),
                &g_Wtf[(size_t)(bn0 + lr + 64) * K2c + Dc + k0 + lc]);
        };

        const int mgP = warp & 3;
        const int ngP = warp >> 2;
        float cP[4][4];
#pragma unroll
        for (int nt = 0; nt < 4; nt++)
#pragma unroll
            for (int r = 0; r < 4; r++) cP[nt][r] = 0.f;

        issueP(0, 0);  CP_COMMIT();
        issueP(1, 32); CP_COMMIT();

#pragma unroll 1
        for (int it = 0; it < NIT; it++) {
            const int st = it & 3;
            const int nx = it + 2;
            if (nx < NIT) issueP(nx & 3, nx * 32);
            CP_COMMIT();
            CP_WAIT2();
            __syncthreads();
#pragma unroll
            for (int kk = 0; kk < 4; kk++) {
                uint32_t af[4];
                af[0] = sm.As[st][mgP*16 + g    ][kk*8 + q    ];
                af[1] = sm.As[st][mgP*16 + g + 8][kk*8 + q    ];
                af[2] = sm.As[st][mgP*16 + g    ][kk*8 + q + 4];
                af[3] = sm.As[st][mgP*16 + g + 8][kk*8 + q + 4];
#pragma unroll
                for (int nt = 0; nt < 4; nt++) {
                    int n = ngP*32 + nt*8 + g;
                    uint32_t b0 = sm.Bs[st][n][kk*8 + q];
                    uint32_t b1 = sm.Bs[st][n][kk*8 + q + 4];
                    asm volatile(
                        "mma.sync.aligned.m16n8k8.row.col.f32.tf32.tf32.f32 "
                        "{%0,%1,%2,%3}, {%4,%5,%6,%7}, {%8,%9}, {%0,%1,%2,%3};\n"
                        : "+f"(cP[nt][0]), "+f"(cP[nt][1]), "+f"(cP[nt][2]), "+f"(cP[nt][3])
                        : "r"(af[0]), "r"(af[1]), "r"(af[2]), "r"(af[3]),
                          "r"(b0), "r"(b1));
                }
            }
        }
        CP_WAIT0();
        __syncthreads();

        // dump P (+bias) to persistent smem
        int r0 = mgP * 16 + g;
#pragma unroll
        for (int nt = 0; nt < 4; nt++) {
            int col = ngP*32 + nt*8 + q*2;
            float b0 = bias[bn0 + col];
            float b1 = bias[bn0 + col + 1];
            sm.P[r0    ][col    ] = cP[nt][0] + b0;
            sm.P[r0    ][col + 1] = cP[nt][1] + b1;
            sm.P[r0 + 8][col    ] = cP[nt][2] + b0;
            sm.P[r0 + 8][col + 1] = cP[nt][3] + b1;
        }
    }
    __syncthreads();

    // ===================== Phase E: 128 x 128 =====================
    const int mgE = warp & 3;     // m-tiles {mgE, mgE+4}
    const int ngE = warp >> 2;
    float cE[2][4][4];
#pragma unroll
    for (int mt = 0; mt < 2; mt++)
#pragma unroll
        for (int nt = 0; nt < 4; nt++)
#pragma unroll
            for (int r = 0; r < 4; r++) cE[mt][nt][r] = 0.f;

    {
        auto issueE = [&](int st, int k0) {
            cpa(asB + soff(st, lr, lc),
                &g_encT[(size_t)(bt0 + lr) * Dc + k0 + lc]);
            cpa(asB + soff(st, lr + 64, lc),
                &g_encT[(size_t)(bt0 + lr + 64) * Dc + k0 + lc]);
            cpa(bsB + soff(st, lr, lc),
                &g_Wtf[(size_t)(bn0 + lr) * K2c + k0 + lc]);
            cpa(bsB + soff(st, lr + 64, lc),
                &g_Wtf[(size_t)(bn0 + lr + 64) * K2c + k0 + lc]);
        };

        issueE(0, 0);  CP_COMMIT();
        issueE(1, 32); CP_COMMIT();

#pragma unroll 1
        for (int it = 0; it < NIT; it++) {
            const int st = it & 3;
            const int nx = it + 2;
            if (nx < NIT) issueE(nx & 3, nx * 32);
            CP_COMMIT();
            CP_WAIT2();
            __syncthreads();
#pragma unroll
            for (int kk = 0; kk < 4; kk++) {
                uint32_t af[2][4];
#pragma unroll
                for (int mt = 0; mt < 2; mt++) {
                    int r0 = (mgE + 4*mt) * 16;
                    af[mt][0] = sm.As[st][r0 + g    ][kk*8 + q    ];
                    af[mt][1] = sm.As[st][r0 + g + 8][kk*8 + q    ];
                    af[mt][2] = sm.As[st][r0 + g    ][kk*8 + q + 4];
                    af[mt][3] = sm.As[st][r0 + g + 8][kk*8 + q + 4];
                }
#pragma unroll
                for (int nt = 0; nt < 4; nt++) {
                    int n = ngE*32 + nt*8 + g;
                    uint32_t b0 = sm.Bs[st][n][kk*8 + q];
                    uint32_t b1 = sm.Bs[st][n][kk*8 + q + 4];
#pragma unroll
                    for (int mt = 0; mt < 2; mt++) {
                        asm volatile(
                            "mma.sync.aligned.m16n8k8.row.col.f32.tf32.tf32.f32 "
                            "{%0,%1,%2,%3}, {%4,%5,%6,%7}, {%8,%9}, {%0,%1,%2,%3};\n"
                            : "+f"(cE[mt][nt][0]), "+f"(cE[mt][nt][1]),
                              "+f"(cE[mt][nt][2]), "+f"(cE[mt][nt][3])
                            : "r"(af[mt][0]), "r"(af[mt][1]), "r"(af[mt][2]), "r"(af[mt][3]),
                              "r"(b0), "r"(b1));
                    }
                }
            }
        }
        CP_WAIT0();
        __syncthreads();
    }

    // ===================== Phase C: expand (4 slabs of 32 t) ===============
    const int vq = lane;
#pragma unroll 1
    for (int s = 0; s < 4; s++) {
#pragma unroll
        for (int mt = 0; mt < 2; mt++) {
            int mtile = mgE + 4 * mt;
            if ((mtile >> 1) == s) {
                int r0 = (mtile & 1) * 16 + g;
#pragma unroll
                for (int nt = 0; nt < 4; nt++) {
                    int col = ngE*32 + nt*8 + q*2;
                    sm.E[r0    ][col    ] = cE[mt][nt][0];
                    sm.E[r0    ][col + 1] = cE[mt][nt][1];
                    sm.E[r0 + 8][col    ] = cE[mt][nt][2];
                    sm.E[r0 + 8][col + 1] = cE[mt][nt][3];
                }
            }
        }
        __syncthreads();

        // warp w stores rows {2w, 2w+1}; per u: 1 LDS + 2 STG.WT
        float4 e0 = ((const float4*)sm.E[warp * 2    ])[vq];
        float4 e1 = ((const float4*)sm.E[warp * 2 + 1])[vq];
        size_t ob0 = (size_t)(bt0 + s * 32 + warp * 2) * (Uc * 256)
                     + blockIdx.x * 32 + vq;
        size_t ob1 = ob0 + (size_t)(Uc * 256);
#pragma unroll 4
        for (int u = 0; u < Uc; u++) {
            float4 p = ((const float4*)sm.P[u])[vq];
            float4 r0, r1;
            r0.x = e0.x + p.x; r0.y = e0.y + p.y; r0.z = e0.z + p.z; r0.w = e0.w + p.w;
            r1.x = e1.x + p.x; r1.y = e1.y + p.y; r1.z = e1.z + p.z; r1.w = e1.w + p.w;
            __stwt(&out[ob0 + (size_t)u * 256], r0);
            __stwt(&out[ob1 + (size_t)u * 256], r1);
        }
        __syncthreads();
    }
}

extern "C" void kernel_launch(void* const* d_in, const int* in_sizes, int n_in,
                              void* d_out, int out_size)
{
    const float* enc  = (const float*)d_in[0];  // [B,T,D]
    const int*   slen = (const int*)  d_in[1];  // [B]
    const float* pred = (const float*)d_in[2];  // [B,U,D]
    const int*   tlen = (const int*)  d_in[3];  // [B]
    const float* W    = (const float*)d_in[4];  // [V, 2D]
    const float* bias = (const float*)d_in[5];  // [V]
    float* out = (float*)d_out;

    int writeTail = (out_size >= (int)((size_t)MOUT * Vc + 16)) ? 1 : 0;

    int nTot = NE4 + NP4 + NW4;
    transform_kernel<<<(nTot + 255) / 256, 256>>>(
        (const float4*)enc, (const float4*)pred, (const float4*)W,
        out, slen, tlen, writeTail);

    int smemBytes = (int)sizeof(Smem);
    cudaFuncSetAttribute(fused_joiner,
                         cudaFuncAttributeMaxDynamicSharedMemorySize, smemBytes);
    fused_joiner<<<dim3(Vc / 128, 2 * Bc), 512, smemBytes>>>(
        bias, (float4*)out);
}